// round 13
// baseline (speedup 1.0000x reference)
#include <cuda_runtime.h>
#include <cuda_fp16.h>
#include <cstdint>

#define Bc 8
#define Lc 2048
#define Dc 1024
#define NL 3
#define KC 4
#define NTOK (Bc * Lc)          // 16384
#define NELEM (Bc * Lc * Dc)    // 16777216

// ---------------------------------------------------------------------------
// Scratch (__device__ globals; allocation-free contract)
// ---------------------------------------------------------------------------
__device__ float g_r[NELEM];
__device__ float g_i[NELEM];
__device__ float g_t[NELEM];
__device__ float g_x[NELEM];
__device__ __half g_ahl[(size_t)NTOK * 2048];        // A (stride 2048; hi cols 0..1023)
__device__ __half g_wh[(size_t)9 * 1024 * 1024];     // 9 weight mats fp16 (18MB)

// ---------------------------------------------------------------------------
// PTX helpers (sm_80-era instructions only: cp.async, ldmatrix, mma.sync)
// ---------------------------------------------------------------------------
__device__ __forceinline__ uint32_t smem_u32(const void* p) {
    uint32_t a;
    asm("{ .reg .u64 t; cvta.to.shared.u64 t, %1; cvt.u32.u64 %0, t; }" : "=r"(a) : "l"(p));
    return a;
}

#define CP_ASYNC16(saddr, gaddr) \
    asm volatile("cp.async.cg.shared.global [%0], [%1], 16;" :: "r"(saddr), "l"(gaddr) : "memory")
#define CP_COMMIT() asm volatile("cp.async.commit_group;" ::: "memory")
#define CP_WAIT(n)  asm volatile("cp.async.wait_group %0;" :: "n"(n) : "memory")

#define LDSM_X4(r0, r1, r2, r3, addr) \
    asm volatile("ldmatrix.sync.aligned.m8n8.x4.shared.b16 {%0,%1,%2,%3}, [%4];" \
        : "=r"(r0), "=r"(r1), "=r"(r2), "=r"(r3) : "r"(addr))

#define MMA16816(d0, d1, d2, d3, a0, a1, a2, a3, b0, b1) \
    asm volatile("mma.sync.aligned.m16n8k16.row.col.f32.f16.f16.f32 " \
        "{%0,%1,%2,%3}, {%4,%5,%6,%7}, {%8,%9}, {%0,%1,%2,%3};" \
        : "+f"(d0), "+f"(d1), "+f"(d2), "+f"(d3) \
        : "r"(a0), "r"(a1), "r"(a2), "r"(a3), "r"(b0), "r"(b1))

// ---------------------------------------------------------------------------
// Weight split: 9 [1024,1024] fp32 -> [1024,1024] fp16
// ---------------------------------------------------------------------------
__global__ void split_w_kernel(const float* __restrict__ wr,
                               const float* __restrict__ wi,
                               const float* __restrict__ wo)
{
    int idx = blockIdx.x * blockDim.x + threadIdx.x;  // 0 .. 9*2^20-1
    int slot = idx >> 20;
    int rem = idx & 0xFFFFF;
    int l = slot / 3, wt = slot % 3;
    const float* src = (wt == 0) ? wr : (wt == 1) ? wi : wo;
    float v = src[(size_t)l * 1048576 + rem];
    g_wh[(size_t)slot * 1048576 + rem] = __float2half(v);
}

// ---------------------------------------------------------------------------
// Layer-0 conv: causal depthwise conv1d -> xc fp32 + ahl fp16
// ---------------------------------------------------------------------------
__global__ void conv_split_kernel(const float* __restrict__ x,
                                  const float* __restrict__ cw,
                                  const float* __restrict__ cb,
                                  float* __restrict__ xc,
                                  __half* __restrict__ ahl)
{
    int idx = blockIdx.x * blockDim.x + threadIdx.x;
    if (idx >= NELEM) return;
    int d = idx & (Dc - 1);
    int t = (idx / Dc) & (Lc - 1);

    float w0 = cw[d * KC + 0];
    float w1 = cw[d * KC + 1];
    float w2 = cw[d * KC + 2];
    float w3 = cw[d * KC + 3];

    const float* xp = x + idx;
    float acc = cb[d];
    acc = fmaf(w3, xp[0], acc);
    if (t >= 1) acc = fmaf(w2, xp[-Dc], acc);
    if (t >= 2) acc = fmaf(w1, xp[-2 * Dc], acc);
    if (t >= 3) acc = fmaf(w0, xp[-3 * Dc], acc);

    xc[idx] = acc;
    size_t m = (size_t)(idx >> 10);
    ahl[m * 2048 + d] = __float2half(acc);
}

// ---------------------------------------------------------------------------
// Fused rmsnorm + conv for layers >= 1 -> xc fp32 + ahl fp16
// ---------------------------------------------------------------------------
__device__ __forceinline__ void block_reduce4(float s[4])
{
    __shared__ float sh[4][8];
    int lane = threadIdx.x & 31, w = threadIdx.x >> 5;
#pragma unroll
    for (int j = 0; j < 4; j++)
#pragma unroll
        for (int o = 16; o; o >>= 1)
            s[j] += __shfl_xor_sync(0xffffffffu, s[j], o);
    if (lane == 0)
#pragma unroll
        for (int j = 0; j < 4; j++) sh[j][w] = s[j];
    __syncthreads();
    if (w == 0) {
        float t[4];
#pragma unroll
        for (int j = 0; j < 4; j++) t[j] = (lane < 8) ? sh[j][lane] : 0.f;
#pragma unroll
        for (int o = 4; o; o >>= 1)
#pragma unroll
            for (int j = 0; j < 4; j++) t[j] += __shfl_xor_sync(0xffffffffu, t[j], o);
        if (lane == 0)
#pragma unroll
            for (int j = 0; j < 4; j++) sh[j][0] = t[j];
    }
    __syncthreads();
#pragma unroll
    for (int j = 0; j < 4; j++) s[j] = sh[j][0];
}

__global__ __launch_bounds__(256, 4)
void norm_conv_split(const float* __restrict__ tb,
                     const float* __restrict__ nw,
                     const float* __restrict__ cw,
                     const float* __restrict__ cb,
                     float* __restrict__ xcout,
                     __half* __restrict__ ahl)
{
    int row = blockIdx.x;              // token index 0..16383
    int b = row >> 11, t = row & 2047;
    int tid = threadIdx.x;

    float4 xv[4];
    float ss[4];
#pragma unroll
    for (int k = 0; k < 4; k++) {
        int tk = t - 3 + k;
        if (tk >= 0) {
            xv[k] = ((const float4*)(tb + ((size_t)(b << 11) + tk) * Dc))[tid];
            ss[k] = xv[k].x * xv[k].x + xv[k].y * xv[k].y +
                    xv[k].z * xv[k].z + xv[k].w * xv[k].w;
        } else {
            xv[k] = make_float4(0.f, 0.f, 0.f, 0.f);
            ss[k] = 0.f;
        }
    }
    block_reduce4(ss);
    float sc[4];
#pragma unroll
    for (int k = 0; k < 4; k++) sc[k] = rsqrtf(ss[k] * (1.0f / Dc) + 1e-6f);

    float4 nwv = ((const float4*)nw)[tid];
    float4 cbv = ((const float4*)cb)[tid];
    float nwa[4] = {nwv.x, nwv.y, nwv.z, nwv.w};
    float cba[4] = {cbv.x, cbv.y, cbv.z, cbv.w};

    size_t m = (size_t)row;
    float4 xo;
    __half2 hh2[2];
#pragma unroll
    for (int j = 0; j < 4; j++) {
        int d = tid * 4 + j;
        float4 cwv = ((const float4*)cw)[d];
        float xj0 = (&xv[0].x)[j], xj1 = (&xv[1].x)[j];
        float xj2 = (&xv[2].x)[j], xj3 = (&xv[3].x)[j];
        float acc = cwv.x * sc[0] * xj0;
        acc = fmaf(cwv.y, sc[1] * xj1, acc);
        acc = fmaf(cwv.z, sc[2] * xj2, acc);
        acc = fmaf(cwv.w, sc[3] * xj3, acc);
        acc = cba[j] + nwa[j] * acc;
        (&xo.x)[j] = acc;
        ((__half*)hh2)[j] = __float2half(acc);
    }
    *(__half2*)(ahl + m * 2048 + tid * 4) = hh2[0];
    *(__half2*)(ahl + m * 2048 + tid * 4 + 2) = hh2[1];
    ((float4*)(xcout + m * Dc))[tid] = xo;
}

// ---------------------------------------------------------------------------
// mma.sync GEMM: C[M,1024] = A[M,K=1024] * W[1024,K]^T   (single fp16 pass)
// CTA tile 256x128 (M x N), 512 threads / 16 warps (4x4 grid of 64x32 tiles),
// 3-stage cp.async pipeline (load c+2 before compute c), 1 CTA/SM.
// A: stride-2048 ahl (hi cols). ACT=1: +bias, sigmoid.
// gridDim.z picks (W0,b0,C0) vs (W1,b1,C1).
// ---------------------------------------------------------------------------
#define TROW 144                          // padded smem row stride (bytes)
#define ATILE_B (256 * TROW)              // 36864
#define WTILE_B (128 * TROW)              // 18432
#define STG 3
#define STAGE_B (ATILE_B + WTILE_B)       // 55296
#define GEMM_SMEM (STG * STAGE_B)         // 165888
#define NCHUNK 16                         // 16 chunks of K=64

template <int ACT>
__global__ __launch_bounds__(512, 1)
void gemm_mma(const __half* __restrict__ A,
              const __half* __restrict__ W0, const __half* __restrict__ W1,
              const float* __restrict__ b0, const float* __restrict__ b1,
              float* __restrict__ C0, float* __restrict__ C1)
{
    extern __shared__ char smem[];
    const uint32_t TILES = smem_u32(smem);

    const int tid = threadIdx.x;
    const int wid = tid >> 5;
    const int lane = tid & 31;

    const int sel = (int)blockIdx.z;
    const __half* W = sel ? W1 : W0;
    const int m0 = blockIdx.y * 256;
    const int n0 = blockIdx.x * 128;

    const int warp_m = (wid >> 2) * 64;    // 4 m-groups of 64
    const int warp_n = (wid & 3) * 32;     // 4 n-groups of 32

    // ldmatrix lane address components
    const int a_row = (lane & 7) + ((lane >> 3) & 1) * 8;
    const int a_kb = ((lane >> 4) & 1) * 16;
    const int b_row = (lane & 7) + ((lane >> 4) & 1) * 8;
    const int b_kb = ((lane >> 3) & 1) * 16;

    float acc[4][4][4];
#pragma unroll
    for (int i = 0; i < 4; i++)
#pragma unroll
        for (int j = 0; j < 4; j++)
#pragma unroll
            for (int k = 0; k < 4; k++) acc[i][j][k] = 0.f;

    // producer: 6 x 16B cp.async per thread per chunk (A 4 + W 2)
    auto load_chunk = [&](int c) {
        int kc = c << 6;
        uint32_t Sb = TILES + (c % STG) * STAGE_B;
#pragma unroll
        for (int i = 0; i < 4; i++) {
            int id = tid + i * 512;
            int row = id >> 3, q = id & 7;         // rows 0..255
            const __half* g = A + (size_t)(m0 + row) * 2048 + kc + q * 8;
            CP_ASYNC16(Sb + row * TROW + q * 16, g);
        }
#pragma unroll
        for (int i = 0; i < 2; i++) {
            int id = tid + i * 512;
            int row = id >> 3, q = id & 7;         // rows 0..127
            const __half* g = W + (size_t)(n0 + row) * 1024 + kc + q * 8;
            CP_ASYNC16(Sb + ATILE_B + row * TROW + q * 16, g);
        }
    };

    load_chunk(0); CP_COMMIT();
    load_chunk(1); CP_COMMIT();

    // 3-stage: load(c+2) issued BEFORE compute(c); one sync per chunk
#pragma unroll 1
    for (int c = 0; c < NCHUNK; c++) {
        CP_WAIT(1);
        __syncthreads();
        if (c + 2 < NCHUNK) load_chunk(c + 2);
        CP_COMMIT();

        uint32_t Sb = TILES + (c % STG) * STAGE_B;
        uint32_t a_base = Sb + (warp_m + a_row) * TROW + a_kb;
        uint32_t b_base = Sb + ATILE_B + (warp_n + b_row) * TROW + b_kb;

#pragma unroll
        for (int ks = 0; ks < 4; ks++) {
            uint32_t bf[4][2];
#pragma unroll
            for (int j = 0; j < 2; j++) {
                LDSM_X4(bf[2 * j][0], bf[2 * j][1], bf[2 * j + 1][0], bf[2 * j + 1][1],
                        b_base + j * 16 * TROW + ks * 32);
            }
            uint32_t af[4][4];
#pragma unroll
            for (int i = 0; i < 4; i++) {
                LDSM_X4(af[i][0], af[i][1], af[i][2], af[i][3],
                        a_base + i * 16 * TROW + ks * 32);
            }
#pragma unroll
            for (int im = 0; im < 4; im++)
#pragma unroll
                for (int in = 0; in < 4; in++)
                    MMA16816(acc[im][in][0], acc[im][in][1], acc[im][in][2], acc[im][in][3],
                             af[im][0], af[im][1], af[im][2], af[im][3],
                             bf[in][0], bf[in][1]);
        }
    }

    // epilogue
    float* C = sel ? C1 : C0;
    const float* bias = sel ? b1 : b0;
    const int g = lane >> 2, tg = lane & 3;
#pragma unroll
    for (int im = 0; im < 4; im++) {
#pragma unroll
        for (int in = 0; in < 4; in++) {
            int row = m0 + warp_m + im * 16 + g;
            int col = n0 + warp_n + in * 8 + tg * 2;
            float v0 = acc[im][in][0], v1 = acc[im][in][1];
            float v2 = acc[im][in][2], v3 = acc[im][in][3];
            if (ACT) {
                float bb0 = bias[col], bb1 = bias[col + 1];
                v0 = 1.0f / (1.0f + __expf(-(v0 + bb0)));
                v1 = 1.0f / (1.0f + __expf(-(v1 + bb1)));
                v2 = 1.0f / (1.0f + __expf(-(v2 + bb0)));
                v3 = 1.0f / (1.0f + __expf(-(v3 + bb1)));
            }
            *(float2*)(C + (size_t)row * 1024 + col) = make_float2(v0, v1);
            *(float2*)(C + (size_t)(row + 8) * 1024 + col) = make_float2(v2, v3);
        }
    }
}

// ---------------------------------------------------------------------------
// Warp-parallel clamped log-space scan, 2 timesteps per lane.
// Warp w owns channel d0+w; lane u handles t=2u, 2u+1 within 64-step chunks.
// Smem row for timestep t is R(t) = (t&1)*32 + (t>>1) so compute-phase reads
// (rows u and 32+u) stay conflict-free at stride 17.
// Writes h (fp16) into ahl for the out-GEMM.
// ---------------------------------------------------------------------------
__global__ __launch_bounds__(512, 2)
void scan_kernel(const float* __restrict__ r_,
                 const float* __restrict__ i_,
                 const float* __restrict__ xc_,
                 const float* __restrict__ la_,
                 __half* __restrict__ ahl)
{
    __shared__ float s_r[64][17];
    __shared__ float s_i[64][17];
    __shared__ float s_x[64][17];
    __shared__ float s_h[64][17];

    const int tid = threadIdx.x;
    const int w = tid >> 5;        // warp 0..15 = channel
    const int u = tid & 31;        // lane
    const int b = blockIdx.y;
    const int d0 = blockIdx.x * 16;

    const int tl = tid >> 4;       // load-phase: timesteps tl and tl+32
    const int dl = tid & 15;       // load-phase: d within group
    const int Ra = ((tl & 1) << 5) + (tl >> 1);        // R(tl)
    const int Rb = Ra + 16;                            // R(tl+32)

    const int dch = d0 + w;        // compute-phase channel
    float la = la_[dch];
    float abase = 1.0f / (1.0f + expf(-la));
    float lga8 = 8.0f * logf(abase);

    float c_carry = 0.f, S_carry = 0.f;

    size_t gbase = ((size_t)b * Lc) * Dc + d0 + dl;        // r,i,xc (stride Dc)
    size_t hbase = ((size_t)b * Lc) * 2048 + d0 + dl;      // ahl (stride 2048)

    float vr0 = r_[gbase + (size_t)tl * Dc];
    float vi0 = i_[gbase + (size_t)tl * Dc];
    float vx0 = xc_[gbase + (size_t)tl * Dc];
    float vr1 = r_[gbase + (size_t)(tl + 32) * Dc];
    float vi1 = i_[gbase + (size_t)(tl + 32) * Dc];
    float vx1 = xc_[gbase + (size_t)(tl + 32) * Dc];

    for (int it = 0; it < Lc / 64; it++) {
        s_r[Ra][dl] = vr0;  s_r[Rb][dl] = vr1;
        s_i[Ra][dl] = vi0;  s_i[Rb][dl] = vi1;
        s_x[Ra][dl] = vx0;  s_x[Rb][dl] = vx1;
        __syncthreads();

        if (it + 1 < Lc / 64) {
            size_t t0 = (size_t)((it + 1) * 64 + tl);
            vr0 = r_[gbase + t0 * Dc];
            vi0 = i_[gbase + t0 * Dc];
            vx0 = xc_[gbase + t0 * Dc];
            vr1 = r_[gbase + (t0 + 32) * Dc];
            vi1 = i_[gbase + (t0 + 32) * Dc];
            vx1 = xc_[gbase + (t0 + 32) * Dc];
        }

        // compute: lane u handles t=2u (row u) and t=2u+1 (row 32+u)
        float r0 = s_r[u][w],      i0 = s_i[u][w],      x0 = s_x[u][w];
        float r1 = s_r[32 + u][w], i1 = s_i[32 + u][w], x1 = s_x[32 + u][w];

        float inc0 = lga8 * r0;
        float inc1 = lga8 * r1;
        float p = inc0 + inc1;
#pragma unroll
        for (int o = 1; o < 32; o <<= 1) {
            float t = __shfl_up_sync(0xffffffffu, p, o);
            if (u >= o) p += t;
        }
        float c1 = c_carry + p;
        float c0 = c1 - inc1;
        float lac0 = fmaxf(c0, -80.f);
        float lac1 = fmaxf(c1, -80.f);
        float A0 = __expf(lac0), A1 = __expf(lac1);
        float w0 = __expf(-lac0), w1 = __expf(-lac1);
        float a0 = __expf(inc0), a1 = __expf(inc1);
        float bt0 = sqrtf(fmaxf(1.f - a0 * a0, 1e-6f)) * (i0 * x0);
        float bt1 = sqrtf(fmaxf(1.f - a1 * a1, 1e-6f)) * (i1 * x1);
        float t0 = bt0 * w0;
        float t1 = bt1 * w1;
        float q = t0 + t1;
#pragma unroll
        for (int o = 1; o < 32; o <<= 1) {
            float t = __shfl_up_sync(0xffffffffu, q, o);
            if (u >= o) q += t;
        }
        float S1 = S_carry + q;
        float S0 = S1 - t1;
        float h0 = A0 * S0;
        float h1 = A1 * S1;
        c_carry = __shfl_sync(0xffffffffu, c1, 31);
        S_carry = __shfl_sync(0xffffffffu, S1, 31);

        s_h[u][w] = h0;            // t=2u     -> row u
        s_h[32 + u][w] = h1;       // t=2u+1   -> row 32+u
        __syncthreads();

        // store: thread covers timesteps tl (row Ra) and tl+32 (row Rb)
        float hv0 = s_h[Ra][dl];
        float hv1 = s_h[Rb][dl];
        size_t trow = (size_t)(it * 64 + tl);
        ahl[hbase + trow * 2048] = __float2half(hv0);
        ahl[hbase + (trow + 32) * 2048] = __float2half(hv1);
    }
}

// ---------------------------------------------------------------------------
// Final fused double-rmsnorm
// ---------------------------------------------------------------------------
__device__ __forceinline__ void block_reduce_sum2(float& a, float& b)
{
    __shared__ float sha[8], shb[8];
    int lane = threadIdx.x & 31, wid = threadIdx.x >> 5;
#pragma unroll
    for (int o = 16; o; o >>= 1) {
        a += __shfl_xor_sync(0xffffffffu, a, o);
        b += __shfl_xor_sync(0xffffffffu, b, o);
    }
    if (lane == 0) { sha[wid] = a; shb[wid] = b; }
    __syncthreads();
    float ta = (lane < (blockDim.x >> 5)) ? sha[lane] : 0.f;
    float tb = (lane < (blockDim.x >> 5)) ? shb[lane] : 0.f;
    if (wid == 0) {
#pragma unroll
        for (int o = 4; o; o >>= 1) {
            ta += __shfl_xor_sync(0xffffffffu, ta, o);
            tb += __shfl_xor_sync(0xffffffffu, tb, o);
        }
        if (lane == 0) { sha[0] = ta; shb[0] = tb; }
    }
    __syncthreads();
    a = sha[0];
    b = shb[0];
}

__global__ void rmsnorm2_kernel(const float* __restrict__ x,
                                const float* __restrict__ w1,
                                const float* __restrict__ w2,
                                float* __restrict__ out)
{
    int row = blockIdx.x;
    int t = threadIdx.x;
    float4 xv = ((const float4*)(x + (size_t)row * Dc))[t];
    float4 w1v = ((const float4*)w1)[t];
    float y0 = xv.x * w1v.x, y1 = xv.y * w1v.y, y2 = xv.z * w1v.z, y3 = xv.w * w1v.w;
    float ss = xv.x * xv.x + xv.y * xv.y + xv.z * xv.z + xv.w * xv.w;
    float ssw = y0 * y0 + y1 * y1 + y2 * y2 + y3 * y3;
    block_reduce_sum2(ss, ssw);
    float sc1 = rsqrtf(ss * (1.0f / Dc) + 1e-6f);
    float sc2 = rsqrtf(ssw * sc1 * sc1 * (1.0f / Dc) + 1e-6f);
    float s = sc1 * sc2;
    float4 w2v = ((const float4*)w2)[t];
    float4 o = make_float4(y0 * w2v.x * s, y1 * w2v.y * s,
                           y2 * w2v.z * s, y3 * w2v.w * s);
    ((float4*)(out + (size_t)row * Dc))[t] = o;
}

// ---------------------------------------------------------------------------
extern "C" void kernel_launch(void* const* d_in, const int* in_sizes, int n_in,
                              void* d_out, int out_size)
{
    (void)in_sizes; (void)n_in; (void)out_size;
    const float* x          = (const float*)d_in[0];
    const float* conv_w     = (const float*)d_in[1];
    const float* conv_b     = (const float*)d_in[2];
    const float* wr_w       = (const float*)d_in[3];
    const float* wr_b       = (const float*)d_in[4];
    const float* wi_w       = (const float*)d_in[5];
    const float* wi_b       = (const float*)d_in[6];
    const float* log_a      = (const float*)d_in[7];
    const float* wo_w       = (const float*)d_in[8];
    const float* norm_w     = (const float*)d_in[9];
    const float* norm_out_w = (const float*)d_in[10];
    float* out = (float*)d_out;

    float *rb, *ib, *tb, *xb;
    __half *ahl, *wh;
    cudaGetSymbolAddress((void**)&rb, g_r);
    cudaGetSymbolAddress((void**)&ib, g_i);
    cudaGetSymbolAddress((void**)&tb, g_t);
    cudaGetSymbolAddress((void**)&xb, g_x);
    cudaGetSymbolAddress((void**)&ahl, g_ahl);
    cudaGetSymbolAddress((void**)&wh, g_wh);

    cudaFuncSetAttribute((const void*)gemm_mma<0>,
                         cudaFuncAttributeMaxDynamicSharedMemorySize, GEMM_SMEM);
    cudaFuncSetAttribute((const void*)gemm_mma<1>,
                         cudaFuncAttributeMaxDynamicSharedMemorySize, GEMM_SMEM);

    // convert all 9 weight matrices once
    split_w_kernel<<<(9 * 1048576) / 256, 256>>>(wr_w, wi_w, wo_w);

    for (int l = 0; l < NL; l++) {
        if (l == 0) {
            conv_split_kernel<<<NELEM / 256, 256>>>(x, conv_w, conv_b, xb, ahl);
        } else {
            norm_conv_split<<<NTOK, 256>>>(tb,
                                           norm_w + (size_t)(l - 1) * Dc,
                                           conv_w + (size_t)l * Dc * KC,
                                           conv_b + (size_t)l * Dc, xb, ahl);
        }

        dim3 gg(Dc / 128, NTOK / 256, 2);
        gemm_mma<1><<<gg, 512, GEMM_SMEM>>>(ahl,
                                            wh + (size_t)(3 * l + 0) * 1048576,
                                            wh + (size_t)(3 * l + 1) * 1048576,
                                            wr_b + (size_t)l * Dc,
                                            wi_b + (size_t)l * Dc,
                                            rb, ib);

        scan_kernel<<<dim3(Dc / 16, Bc), 512>>>(rb, ib, xb,
                                                log_a + (size_t)l * Dc, ahl);

        dim3 go(Dc / 128, NTOK / 256, 1);
        gemm_mma<0><<<go, 512, GEMM_SMEM>>>(ahl,
                                            wh + (size_t)(3 * l + 2) * 1048576,
                                            wh + (size_t)(3 * l + 2) * 1048576,
                                            nullptr, nullptr, tb, tb);
    }

    rmsnorm2_kernel<<<NTOK, 256>>>(tb, norm_w + (size_t)(NL - 1) * Dc,
                                   norm_out_w, out);
}

// round 14
// speedup vs baseline: 1.0427x; 1.0427x over previous
#include <cuda_runtime.h>
#include <cuda_fp16.h>
#include <cstdint>

#define Bc 8
#define Lc 2048
#define Dc 1024
#define NL 3
#define KC 4
#define NTOK (Bc * Lc)          // 16384
#define NELEM (Bc * Lc * Dc)    // 16777216

// ---------------------------------------------------------------------------
// Scratch (__device__ globals; allocation-free contract)
// ---------------------------------------------------------------------------
__device__ float g_r[NELEM];                         // gate r
__device__ float g_ix[NELEM];                        // fused i * xc
__device__ float g_t[NELEM];
__device__ float g_x[NELEM];
__device__ __half g_ahl[(size_t)NTOK * 2048];        // A (stride 2048; hi cols 0..1023)
__device__ __half g_wh[(size_t)9 * 1024 * 1024];     // 9 weight mats fp16 (18MB)

// ---------------------------------------------------------------------------
// PTX helpers (sm_80-era instructions only: cp.async, ldmatrix, mma.sync)
// ---------------------------------------------------------------------------
__device__ __forceinline__ uint32_t smem_u32(const void* p) {
    uint32_t a;
    asm("{ .reg .u64 t; cvta.to.shared.u64 t, %1; cvt.u32.u64 %0, t; }" : "=r"(a) : "l"(p));
    return a;
}

#define CP_ASYNC16(saddr, gaddr) \
    asm volatile("cp.async.cg.shared.global [%0], [%1], 16;" :: "r"(saddr), "l"(gaddr) : "memory")
#define CP_COMMIT() asm volatile("cp.async.commit_group;" ::: "memory")
#define CP_WAIT(n)  asm volatile("cp.async.wait_group %0;" :: "n"(n) : "memory")

#define LDSM_X4(r0, r1, r2, r3, addr) \
    asm volatile("ldmatrix.sync.aligned.m8n8.x4.shared.b16 {%0,%1,%2,%3}, [%4];" \
        : "=r"(r0), "=r"(r1), "=r"(r2), "=r"(r3) : "r"(addr))

#define MMA16816(d0, d1, d2, d3, a0, a1, a2, a3, b0, b1) \
    asm volatile("mma.sync.aligned.m16n8k16.row.col.f32.f16.f16.f32 " \
        "{%0,%1,%2,%3}, {%4,%5,%6,%7}, {%8,%9}, {%0,%1,%2,%3};" \
        : "+f"(d0), "+f"(d1), "+f"(d2), "+f"(d3) \
        : "r"(a0), "r"(a1), "r"(a2), "r"(a3), "r"(b0), "r"(b1))

// ---------------------------------------------------------------------------
// Weight split: 9 [1024,1024] fp32 -> [1024,1024] fp16
// ---------------------------------------------------------------------------
__global__ void split_w_kernel(const float* __restrict__ wr,
                               const float* __restrict__ wi,
                               const float* __restrict__ wo)
{
    int idx = blockIdx.x * blockDim.x + threadIdx.x;  // 0 .. 9*2^20-1
    int slot = idx >> 20;
    int rem = idx & 0xFFFFF;
    int l = slot / 3, wt = slot % 3;
    const float* src = (wt == 0) ? wr : (wt == 1) ? wi : wo;
    float v = src[(size_t)l * 1048576 + rem];
    g_wh[(size_t)slot * 1048576 + rem] = __float2half(v);
}

// ---------------------------------------------------------------------------
// Layer-0 conv: causal depthwise conv1d -> xc fp32 + ahl fp16
// ---------------------------------------------------------------------------
__global__ void conv_split_kernel(const float* __restrict__ x,
                                  const float* __restrict__ cw,
                                  const float* __restrict__ cb,
                                  float* __restrict__ xc,
                                  __half* __restrict__ ahl)
{
    int idx = blockIdx.x * blockDim.x + threadIdx.x;
    if (idx >= NELEM) return;
    int d = idx & (Dc - 1);
    int t = (idx / Dc) & (Lc - 1);

    float w0 = cw[d * KC + 0];
    float w1 = cw[d * KC + 1];
    float w2 = cw[d * KC + 2];
    float w3 = cw[d * KC + 3];

    const float* xp = x + idx;
    float acc = cb[d];
    acc = fmaf(w3, xp[0], acc);
    if (t >= 1) acc = fmaf(w2, xp[-Dc], acc);
    if (t >= 2) acc = fmaf(w1, xp[-2 * Dc], acc);
    if (t >= 3) acc = fmaf(w0, xp[-3 * Dc], acc);

    xc[idx] = acc;
    size_t m = (size_t)(idx >> 10);
    ahl[m * 2048 + d] = __float2half(acc);
}

// ---------------------------------------------------------------------------
// Fused rmsnorm + conv for layers >= 1 -> xc fp32 + ahl fp16
// ---------------------------------------------------------------------------
__device__ __forceinline__ void block_reduce4(float s[4])
{
    __shared__ float sh[4][8];
    int lane = threadIdx.x & 31, w = threadIdx.x >> 5;
#pragma unroll
    for (int j = 0; j < 4; j++)
#pragma unroll
        for (int o = 16; o; o >>= 1)
            s[j] += __shfl_xor_sync(0xffffffffu, s[j], o);
    if (lane == 0)
#pragma unroll
        for (int j = 0; j < 4; j++) sh[j][w] = s[j];
    __syncthreads();
    if (w == 0) {
        float t[4];
#pragma unroll
        for (int j = 0; j < 4; j++) t[j] = (lane < 8) ? sh[j][lane] : 0.f;
#pragma unroll
        for (int o = 4; o; o >>= 1)
#pragma unroll
            for (int j = 0; j < 4; j++) t[j] += __shfl_xor_sync(0xffffffffu, t[j], o);
        if (lane == 0)
#pragma unroll
            for (int j = 0; j < 4; j++) sh[j][0] = t[j];
    }
    __syncthreads();
#pragma unroll
    for (int j = 0; j < 4; j++) s[j] = sh[j][0];
}

__global__ __launch_bounds__(256, 4)
void norm_conv_split(const float* __restrict__ tb,
                     const float* __restrict__ nw,
                     const float* __restrict__ cw,
                     const float* __restrict__ cb,
                     float* __restrict__ xcout,
                     __half* __restrict__ ahl)
{
    int row = blockIdx.x;              // token index 0..16383
    int b = row >> 11, t = row & 2047;
    int tid = threadIdx.x;

    float4 xv[4];
    float ss[4];
#pragma unroll
    for (int k = 0; k < 4; k++) {
        int tk = t - 3 + k;
        if (tk >= 0) {
            xv[k] = ((const float4*)(tb + ((size_t)(b << 11) + tk) * Dc))[tid];
            ss[k] = xv[k].x * xv[k].x + xv[k].y * xv[k].y +
                    xv[k].z * xv[k].z + xv[k].w * xv[k].w;
        } else {
            xv[k] = make_float4(0.f, 0.f, 0.f, 0.f);
            ss[k] = 0.f;
        }
    }
    block_reduce4(ss);
    float sc[4];
#pragma unroll
    for (int k = 0; k < 4; k++) sc[k] = rsqrtf(ss[k] * (1.0f / Dc) + 1e-6f);

    float4 nwv = ((const float4*)nw)[tid];
    float4 cbv = ((const float4*)cb)[tid];
    float nwa[4] = {nwv.x, nwv.y, nwv.z, nwv.w};
    float cba[4] = {cbv.x, cbv.y, cbv.z, cbv.w};

    size_t m = (size_t)row;
    float4 xo;
    __half2 hh2[2];
#pragma unroll
    for (int j = 0; j < 4; j++) {
        int d = tid * 4 + j;
        float4 cwv = ((const float4*)cw)[d];
        float xj0 = (&xv[0].x)[j], xj1 = (&xv[1].x)[j];
        float xj2 = (&xv[2].x)[j], xj3 = (&xv[3].x)[j];
        float acc = cwv.x * sc[0] * xj0;
        acc = fmaf(cwv.y, sc[1] * xj1, acc);
        acc = fmaf(cwv.z, sc[2] * xj2, acc);
        acc = fmaf(cwv.w, sc[3] * xj3, acc);
        acc = cba[j] + nwa[j] * acc;
        (&xo.x)[j] = acc;
        ((__half*)hh2)[j] = __float2half(acc);
    }
    *(__half2*)(ahl + m * 2048 + tid * 4) = hh2[0];
    *(__half2*)(ahl + m * 2048 + tid * 4 + 2) = hh2[1];
    ((float4*)(xcout + m * Dc))[tid] = xo;
}

// ---------------------------------------------------------------------------
// mma.sync GEMM: C[M,1024] = A[M,K=1024] * W[1024,K]^T   (single fp16 pass)
// A layout: hi cols 0..1023 of stride-2048 ahl; W fp16.
// CTA tile 128x128, 3-stage cp.async pipeline, 8 warps (32x64 each), 2 CTA/SM.
// ACT=1: +bias, sigmoid; z-slice 1 (i-gate) additionally multiplies by xc
// so the stored value is i*xc (the only form the scan consumes).
// gridDim.z picks (W0,b0,C0) vs (W1,b1,C1).
// ---------------------------------------------------------------------------
#define TROW 144                          // padded smem row stride (bytes)
#define TILE_B (128 * TROW)               // 18432
#define STG 3
#define STAGE_B (2 * TILE_B)              // A + W
#define GEMM_SMEM (STG * STAGE_B)         // 110592
#define NCHUNK 16                         // 16 chunks of K=64

template <int ACT>
__global__ __launch_bounds__(256, 2)
void gemm_mma(const __half* __restrict__ A,
              const __half* __restrict__ W0, const __half* __restrict__ W1,
              const float* __restrict__ b0, const float* __restrict__ b1,
              const float* __restrict__ XC,
              float* __restrict__ C0, float* __restrict__ C1)
{
    extern __shared__ char smem[];
    const uint32_t TILES = smem_u32(smem);

    const int tid = threadIdx.x;
    const int wid = tid >> 5;
    const int lane = tid & 31;

    const int sel = (int)blockIdx.z;
    const __half* W = sel ? W1 : W0;
    const int m0 = blockIdx.y * 128;
    const int n0 = blockIdx.x * 128;

    const int warp_m = (wid >> 1) * 32;
    const int warp_n = (wid & 1) * 64;

    // ldmatrix lane address components
    const int a_row = (lane & 7) + ((lane >> 3) & 1) * 8;
    const int a_kb = ((lane >> 4) & 1) * 16;
    const int b_row = (lane & 7) + ((lane >> 4) & 1) * 8;
    const int b_kb = ((lane >> 3) & 1) * 16;

    float acc[2][8][4];
#pragma unroll
    for (int i = 0; i < 2; i++)
#pragma unroll
        for (int j = 0; j < 8; j++)
#pragma unroll
            for (int k = 0; k < 4; k++) acc[i][j][k] = 0.f;

    auto load_chunk = [&](int c) {
        int kc = c << 6;
        uint32_t Sb = TILES + (c % STG) * STAGE_B;
#pragma unroll
        for (int i = 0; i < 4; i++) {
            int id = tid + i * 256;
            int row = id >> 3, q = id & 7;
            const __half* g = A + (size_t)(m0 + row) * 2048 + kc + q * 8;
            CP_ASYNC16(Sb + row * TROW + q * 16, g);
        }
#pragma unroll
        for (int i = 0; i < 4; i++) {
            int id = tid + i * 256;
            int row = id >> 3, q = id & 7;
            const __half* g = W + (size_t)(n0 + row) * 1024 + kc + q * 8;
            CP_ASYNC16(Sb + TILE_B + row * TROW + q * 16, g);
        }
    };

    load_chunk(0); CP_COMMIT();
    load_chunk(1); CP_COMMIT();

    // 3-stage: load(c+2) issued BEFORE compute(c); one sync per chunk
#pragma unroll 1
    for (int c = 0; c < NCHUNK; c++) {
        CP_WAIT(1);
        __syncthreads();
        if (c + 2 < NCHUNK) load_chunk(c + 2);
        CP_COMMIT();

        uint32_t Sb = TILES + (c % STG) * STAGE_B;
        uint32_t ah_base = Sb + (warp_m + a_row) * TROW + a_kb;
        uint32_t b_base = Sb + TILE_B + (warp_n + b_row) * TROW + b_kb;

#pragma unroll
        for (int ks = 0; ks < 4; ks++) {
            uint32_t bf[8][2];
#pragma unroll
            for (int j = 0; j < 4; j++) {
                LDSM_X4(bf[2 * j][0], bf[2 * j][1], bf[2 * j + 1][0], bf[2 * j + 1][1],
                        b_base + j * 16 * TROW + ks * 32);
            }
            uint32_t af[2][4];
            LDSM_X4(af[0][0], af[0][1], af[0][2], af[0][3], ah_base + ks * 32);
            LDSM_X4(af[1][0], af[1][1], af[1][2], af[1][3], ah_base + 16 * TROW + ks * 32);
#pragma unroll
            for (int im = 0; im < 2; im++)
#pragma unroll
                for (int in = 0; in < 8; in++)
                    MMA16816(acc[im][in][0], acc[im][in][1], acc[im][in][2], acc[im][in][3],
                             af[im][0], af[im][1], af[im][2], af[im][3],
                             bf[in][0], bf[in][1]);
        }
    }

    // epilogue
    float* C = sel ? C1 : C0;
    const float* bias = sel ? b1 : b0;
    const int g = lane >> 2, tg = lane & 3;
#pragma unroll
    for (int im = 0; im < 2; im++) {
#pragma unroll
        for (int in = 0; in < 8; in++) {
            int row = m0 + warp_m + im * 16 + g;
            int col = n0 + warp_n + in * 8 + tg * 2;
            float v0 = acc[im][in][0], v1 = acc[im][in][1];
            float v2 = acc[im][in][2], v3 = acc[im][in][3];
            if (ACT) {
                float bb0 = bias[col], bb1 = bias[col + 1];
                v0 = 1.0f / (1.0f + __expf(-(v0 + bb0)));
                v1 = 1.0f / (1.0f + __expf(-(v1 + bb1)));
                v2 = 1.0f / (1.0f + __expf(-(v2 + bb0)));
                v3 = 1.0f / (1.0f + __expf(-(v3 + bb1)));
                if (sel) {
                    // i-gate: store i * xc (bitwise-identical to scan-side product)
                    float2 x01 = *(const float2*)(XC + (size_t)row * 1024 + col);
                    float2 x23 = *(const float2*)(XC + (size_t)(row + 8) * 1024 + col);
                    v0 *= x01.x; v1 *= x01.y;
                    v2 *= x23.x; v3 *= x23.y;
                }
            }
            *(float2*)(C + (size_t)row * 1024 + col) = make_float2(v0, v1);
            *(float2*)(C + (size_t)(row + 8) * 1024 + col) = make_float2(v2, v3);
        }
    }
}

// ---------------------------------------------------------------------------
// Warp-parallel clamped log-space scan, 2 timesteps per lane.
// Inputs: r (gate) and ix = i*xc (fused in gate-GEMM epilogue).
// Warp w owns channel d0+w; lane u handles t=2u, 2u+1 within 64-step chunks.
// Smem row for timestep t is R(t) = (t&1)*32 + (t>>1) so compute-phase reads
// (rows u and 32+u) stay conflict-free at stride 17.
// Writes h (fp16) into ahl for the out-GEMM.
// ---------------------------------------------------------------------------
__global__ __launch_bounds__(512, 2)
void scan_kernel(const float* __restrict__ r_,
                 const float* __restrict__ ix_,
                 const float* __restrict__ la_,
                 __half* __restrict__ ahl)
{
    __shared__ float s_r[64][17];
    __shared__ float s_i[64][17];
    __shared__ float s_h[64][17];

    const int tid = threadIdx.x;
    const int w = tid >> 5;        // warp 0..15 = channel
    const int u = tid & 31;        // lane
    const int b = blockIdx.y;
    const int d0 = blockIdx.x * 16;

    const int tl = tid >> 4;       // load-phase: timesteps tl and tl+32
    const int dl = tid & 15;       // load-phase: d within group
    const int Ra = ((tl & 1) << 5) + (tl >> 1);        // R(tl)
    const int Rb = Ra + 16;                            // R(tl+32)

    const int dch = d0 + w;        // compute-phase channel
    float la = la_[dch];
    float abase = 1.0f / (1.0f + expf(-la));
    float lga8 = 8.0f * logf(abase);

    float c_carry = 0.f, S_carry = 0.f;

    size_t gbase = ((size_t)b * Lc) * Dc + d0 + dl;        // r,ix (stride Dc)
    size_t hbase = ((size_t)b * Lc) * 2048 + d0 + dl;      // ahl (stride 2048)

    float vr0 = r_[gbase + (size_t)tl * Dc];
    float vi0 = ix_[gbase + (size_t)tl * Dc];
    float vr1 = r_[gbase + (size_t)(tl + 32) * Dc];
    float vi1 = ix_[gbase + (size_t)(tl + 32) * Dc];

    for (int it = 0; it < Lc / 64; it++) {
        s_r[Ra][dl] = vr0;  s_r[Rb][dl] = vr1;
        s_i[Ra][dl] = vi0;  s_i[Rb][dl] = vi1;
        __syncthreads();

        if (it + 1 < Lc / 64) {
            size_t t0 = (size_t)((it + 1) * 64 + tl);
            vr0 = r_[gbase + t0 * Dc];
            vi0 = ix_[gbase + t0 * Dc];
            vr1 = r_[gbase + (t0 + 32) * Dc];
            vi1 = ix_[gbase + (t0 + 32) * Dc];
        }

        // compute: lane u handles t=2u (row u) and t=2u+1 (row 32+u)
        float r0 = s_r[u][w],      ix0 = s_i[u][w];
        float r1 = s_r[32 + u][w], ix1 = s_i[32 + u][w];

        float inc0 = lga8 * r0;
        float inc1 = lga8 * r1;
        float p = inc0 + inc1;
#pragma unroll
        for (int o = 1; o < 32; o <<= 1) {
            float t = __shfl_up_sync(0xffffffffu, p, o);
            if (u >= o) p += t;
        }
        float c1 = c_carry + p;
        float c0 = c1 - inc1;
        float lac0 = fmaxf(c0, -80.f);
        float lac1 = fmaxf(c1, -80.f);
        float A0 = __expf(lac0), A1 = __expf(lac1);
        float w0 = __expf(-lac0), w1 = __expf(-lac1);
        float a0 = __expf(inc0), a1 = __expf(inc1);
        float bt0 = sqrtf(fmaxf(1.f - a0 * a0, 1e-6f)) * ix0;
        float bt1 = sqrtf(fmaxf(1.f - a1 * a1, 1e-6f)) * ix1;
        float t0 = bt0 * w0;
        float t1 = bt1 * w1;
        float q = t0 + t1;
#pragma unroll
        for (int o = 1; o < 32; o <<= 1) {
            float t = __shfl_up_sync(0xffffffffu, q, o);
            if (u >= o) q += t;
        }
        float S1 = S_carry + q;
        float S0 = S1 - t1;
        float h0 = A0 * S0;
        float h1 = A1 * S1;
        c_carry = __shfl_sync(0xffffffffu, c1, 31);
        S_carry = __shfl_sync(0xffffffffu, S1, 31);

        s_h[u][w] = h0;            // t=2u     -> row u
        s_h[32 + u][w] = h1;       // t=2u+1   -> row 32+u
        __syncthreads();

        // store: thread covers timesteps tl (row Ra) and tl+32 (row Rb)
        float hv0 = s_h[Ra][dl];
        float hv1 = s_h[Rb][dl];
        size_t trow = (size_t)(it * 64 + tl);
        ahl[hbase + trow * 2048] = __float2half(hv0);
        ahl[hbase + (trow + 32) * 2048] = __float2half(hv1);
    }
}

// ---------------------------------------------------------------------------
// Final fused double-rmsnorm
// ---------------------------------------------------------------------------
__device__ __forceinline__ void block_reduce_sum2(float& a, float& b)
{
    __shared__ float sha[8], shb[8];
    int lane = threadIdx.x & 31, wid = threadIdx.x >> 5;
#pragma unroll
    for (int o = 16; o; o >>= 1) {
        a += __shfl_xor_sync(0xffffffffu, a, o);
        b += __shfl_xor_sync(0xffffffffu, b, o);
    }
    if (lane == 0) { sha[wid] = a; shb[wid] = b; }
    __syncthreads();
    float ta = (lane < (blockDim.x >> 5)) ? sha[lane] : 0.f;
    float tb = (lane < (blockDim.x >> 5)) ? shb[lane] : 0.f;
    if (wid == 0) {
#pragma unroll
        for (int o = 4; o; o >>= 1) {
            ta += __shfl_xor_sync(0xffffffffu, ta, o);
            tb += __shfl_xor_sync(0xffffffffu, tb, o);
        }
        if (lane == 0) { sha[0] = ta; shb[0] = tb; }
    }
    __syncthreads();
    a = sha[0];
    b = shb[0];
}

__global__ void rmsnorm2_kernel(const float* __restrict__ x,
                                const float* __restrict__ w1,
                                const float* __restrict__ w2,
                                float* __restrict__ out)
{
    int row = blockIdx.x;
    int t = threadIdx.x;
    float4 xv = ((const float4*)(x + (size_t)row * Dc))[t];
    float4 w1v = ((const float4*)w1)[t];
    float y0 = xv.x * w1v.x, y1 = xv.y * w1v.y, y2 = xv.z * w1v.z, y3 = xv.w * w1v.w;
    float ss = xv.x * xv.x + xv.y * xv.y + xv.z * xv.z + xv.w * xv.w;
    float ssw = y0 * y0 + y1 * y1 + y2 * y2 + y3 * y3;
    block_reduce_sum2(ss, ssw);
    float sc1 = rsqrtf(ss * (1.0f / Dc) + 1e-6f);
    float sc2 = rsqrtf(ssw * sc1 * sc1 * (1.0f / Dc) + 1e-6f);
    float s = sc1 * sc2;
    float4 w2v = ((const float4*)w2)[t];
    float4 o = make_float4(y0 * w2v.x * s, y1 * w2v.y * s,
                           y2 * w2v.z * s, y3 * w2v.w * s);
    ((float4*)(out + (size_t)row * Dc))[t] = o;
}

// ---------------------------------------------------------------------------
extern "C" void kernel_launch(void* const* d_in, const int* in_sizes, int n_in,
                              void* d_out, int out_size)
{
    (void)in_sizes; (void)n_in; (void)out_size;
    const float* x          = (const float*)d_in[0];
    const float* conv_w     = (const float*)d_in[1];
    const float* conv_b     = (const float*)d_in[2];
    const float* wr_w       = (const float*)d_in[3];
    const float* wr_b       = (const float*)d_in[4];
    const float* wi_w       = (const float*)d_in[5];
    const float* wi_b       = (const float*)d_in[6];
    const float* log_a      = (const float*)d_in[7];
    const float* wo_w       = (const float*)d_in[8];
    const float* norm_w     = (const float*)d_in[9];
    const float* norm_out_w = (const float*)d_in[10];
    float* out = (float*)d_out;

    float *rb, *ixb, *tb, *xb;
    __half *ahl, *wh;
    cudaGetSymbolAddress((void**)&rb, g_r);
    cudaGetSymbolAddress((void**)&ixb, g_ix);
    cudaGetSymbolAddress((void**)&tb, g_t);
    cudaGetSymbolAddress((void**)&xb, g_x);
    cudaGetSymbolAddress((void**)&ahl, g_ahl);
    cudaGetSymbolAddress((void**)&wh, g_wh);

    cudaFuncSetAttribute((const void*)gemm_mma<0>,
                         cudaFuncAttributeMaxDynamicSharedMemorySize, GEMM_SMEM);
    cudaFuncSetAttribute((const void*)gemm_mma<1>,
                         cudaFuncAttributeMaxDynamicSharedMemorySize, GEMM_SMEM);

    // convert all 9 weight matrices once
    split_w_kernel<<<(9 * 1048576) / 256, 256>>>(wr_w, wi_w, wo_w);

    for (int l = 0; l < NL; l++) {
        if (l == 0) {
            conv_split_kernel<<<NELEM / 256, 256>>>(x, conv_w, conv_b, xb, ahl);
        } else {
            norm_conv_split<<<NTOK, 256>>>(tb,
                                           norm_w + (size_t)(l - 1) * Dc,
                                           conv_w + (size_t)l * Dc * KC,
                                           conv_b + (size_t)l * Dc, xb, ahl);
        }

        dim3 gg(Dc / 128, NTOK / 128, 2);
        gemm_mma<1><<<gg, 256, GEMM_SMEM>>>(ahl,
                                            wh + (size_t)(3 * l + 0) * 1048576,
                                            wh + (size_t)(3 * l + 1) * 1048576,
                                            wr_b + (size_t)l * Dc,
                                            wi_b + (size_t)l * Dc,
                                            xb,
                                            rb, ixb);

        scan_kernel<<<dim3(Dc / 16, Bc), 512>>>(rb, ixb,
                                                log_a + (size_t)l * Dc, ahl);

        dim3 go(Dc / 128, NTOK / 128, 1);
        gemm_mma<0><<<go, 256, GEMM_SMEM>>>(ahl,
                                            wh + (size_t)(3 * l + 2) * 1048576,
                                            wh + (size_t)(3 * l + 2) * 1048576,
                                            nullptr, nullptr, nullptr, tb, tb);
    }

    rmsnorm2_kernel<<<NTOK, 256>>>(tb, norm_w + (size_t)(NL - 1) * Dc,
                                   norm_out_w, out);
}